// round 11
// baseline (speedup 1.0000x reference)
#include <cuda_runtime.h>
#include <cstdint>

#define BB 4
#define TT 4096
#define DD 2048
#define BOT 256

// ------------------------- scratch (device globals) -------------------------
__device__ float g_scores[(size_t)BB * TT * TT];   // 256 MB scores -> combined (tf32)
__device__ float g_hdcT[(size_t)BB * DD * TT];     // 128 MB hdc^T (tf32)
__device__ float g_qk[(size_t)BB * TT * 2 * BOT];  // 32 MB  q | k (tf32)
__device__ float g_w[2 * BOT * DD];                // 4 MB   packed [Wq;Wk] (tf32)
__device__ float g_bias[2 * BOT];

__device__ __forceinline__ float to_tf32(float x) {
    uint32_t u;
    asm("cvt.rna.tf32.f32 %0, %1;" : "=r"(u) : "f"(x));
    return __uint_as_float(u);
}
__device__ __forceinline__ uint32_t tf32u(uint32_t x) {
    uint32_t u;
    asm("cvt.rna.tf32.f32 %0, %1;" : "=r"(u) : "f"(__uint_as_float(x)));
    return u;
}
__device__ __forceinline__ uint32_t smem_u32(const void* p) {
    uint32_t a;
    asm("{ .reg .u64 t; cvta.to.shared.u64 t, %1; cvt.u32.u64 %0, t; }" : "=r"(a) : "l"(p));
    return a;
}
__device__ __forceinline__ void cpa16(uint32_t dst, const void* src) {
    asm volatile("cp.async.cg.shared.global [%0], [%1], 16;" :: "r"(dst), "l"(src));
}
__device__ __forceinline__ void ldmx4(uint32_t* d, uint32_t addr) {
    asm volatile("ldmatrix.sync.aligned.m8n8.x4.shared.b16 {%0,%1,%2,%3}, [%4];"
                 : "=r"(d[0]), "=r"(d[1]), "=r"(d[2]), "=r"(d[3]) : "r"(addr));
}

// ------------------------------- small kernels ------------------------------
__global__ void pack_w(const float* __restrict__ Wq, const float* __restrict__ Wk,
                       const float* __restrict__ bq, const float* __restrict__ bk) {
    for (int i = blockIdx.x * blockDim.x + threadIdx.x; i < 2 * BOT * DD;
         i += gridDim.x * blockDim.x) {
        int n = i / DD, k = i - n * DD;
        g_w[i] = to_tf32((n < BOT) ? Wq[n * DD + k] : Wk[(n - BOT) * DD + k]);
    }
    int j = blockIdx.x * blockDim.x + threadIdx.x;
    if (j < 2 * BOT) g_bias[j] = (j < BOT) ? bq[j] : bk[j - BOT];
}

// transpose + round: writes g_hdcT (D-major, tf32)
__global__ __launch_bounds__(256) void transpose_cvt(const float* __restrict__ hdc) {
    __shared__ float tile[32][33];
    const int b = blockIdx.z;
    const int t0 = blockIdx.x * 32, d0 = blockIdx.y * 32;
    const float* src = hdc + (long)b * TT * DD;
    float* dstT = g_hdcT + (long)b * DD * TT;
    const int x = threadIdx.x, y = threadIdx.y;  // (32,8)
    #pragma unroll
    for (int s = 0; s < 32; s += 8)
        tile[y + s][x] = to_tf32(src[(long)(t0 + y + s) * DD + d0 + x]);
    __syncthreads();
    #pragma unroll
    for (int s = 0; s < 32; s += 8)
        dstT[(long)(d0 + y + s) * TT + t0 + x] = tile[x][y + s];
}

// --------------------- pipelined TF32 mma.sync GEMM ------------------------
// C[M,N] = A[M,K] @ B[N,K]^T, both K-major. ldmatrix fragment loads.
// Tile 128(M) x 128(N) x 32(K), 512 threads (16 warps, 32x32 warp tiles),
// 2 CTAs/SM, 3-stage cp.async, 1 sync per chunk.
// MODE 0: plain; 1: +bias, tf32-round (q/k); 2: mask(j<=i-4)*scale, skip dead
// CVTA: round A-fragments to tf32 in registers (A not pre-rounded)
#define Bb_M 128
#define Bb_N 128
#define Bb_K 32
#define NTH 512
#define STG 3
#define A_STAGE (Bb_M * Bb_K)
#define B_STAGE (Bb_N * Bb_K)
#define SMEM_BYTES (STG * (A_STAGE + B_STAGE) * 4)  // 98304

template <int MODE, bool CVTA>
__global__ __launch_bounds__(NTH, 2) void gemm_mma(
    const float* __restrict__ A, const float* __restrict__ Bm, float* __restrict__ C,
    int K, int lda, int ldb, int ldc, long sA, long sB, long sC, float scale) {
    const int m0 = blockIdx.y * Bb_M;
    const int n0 = blockIdx.x * Bb_N;
    if (MODE == 2 && n0 > m0 + 123) return;  // fully masked: never read downstream

    A += (long)blockIdx.z * sA + (long)m0 * lda;
    Bm += (long)blockIdx.z * sB + (long)n0 * ldb;
    C += (long)blockIdx.z * sC;

    extern __shared__ float smem[];
    const uint32_t sbA = smem_u32(smem);
    const uint32_t sbB = sbA + STG * A_STAGE * 4;

    const int t = threadIdx.x;
    const int warp = t >> 5, lane = t & 31;
    const int wm = warp >> 2, wn = warp & 3;  // 4 x 4 warps -> 32x32 each
    const int g = lane >> 2, tg = lane & 3;

    // ldmatrix address precompute (swizzle: chunk c of row r at (c^(r&7))<<4)
    uint32_t arow[2], axor[2];
    #pragma unroll
    for (int mi = 0; mi < 2; mi++) {
        int row = wm * 32 + mi * 16 + (lane & 15);
        arow[mi] = row * 128;
        axor[mi] = (((lane >> 4) << 4) ^ ((row & 7) << 4));
    }
    uint32_t brow[2], bxor[2];
    #pragma unroll
    for (int np = 0; np < 2; np++) {
        int row = wn * 32 + np * 16 + ((lane >> 4) << 3) + (lane & 7);
        brow[np] = row * 128;
        bxor[np] = ((((lane >> 3) & 1) << 4) ^ ((row & 7) << 4));
    }

    const int NC = K >> 5;

    auto load_stage = [&](int s, int kc) {
        const int k0 = kc << 5;
        const uint32_t ab = sbA + s * (A_STAGE * 4);
        const uint32_t bb = sbB + s * (B_STAGE * 4);
        #pragma unroll
        for (int q = 0; q < 2; ++q) {  // A: 128x32 = 1024 x 16B
            int u = t + q * NTH, row = u >> 3, cc = u & 7;
            cpa16(ab + row * 128 + ((cc ^ (row & 7)) << 4),
                  A + (long)row * lda + k0 + cc * 4);
        }
        #pragma unroll
        for (int q = 0; q < 2; ++q) {  // B: 128x32 = 1024 x 16B
            int u = t + q * NTH, row = u >> 3, cc = u & 7;
            cpa16(bb + row * 128 + ((cc ^ (row & 7)) << 4),
                  Bm + (long)row * ldb + k0 + cc * 4);
        }
        asm volatile("cp.async.commit_group;" ::: "memory");
    };

    float acc[2][4][4];
    #pragma unroll
    for (int i = 0; i < 2; i++)
        #pragma unroll
        for (int j = 0; j < 4; j++)
            #pragma unroll
            for (int r = 0; r < 4; r++) acc[i][j][r] = 0.f;

    load_stage(0, 0);
    load_stage(1, 1);

    for (int c = 0; c < NC; ++c) {
        if (c + 1 < NC) asm volatile("cp.async.wait_group 1;" ::: "memory");
        else asm volatile("cp.async.wait_group 0;" ::: "memory");
        __syncthreads();
        if (c + 2 < NC) load_stage((c + 2) % STG, c + 2);

        const int s = c % STG;
        const uint32_t Ab = sbA + s * (A_STAGE * 4);
        const uint32_t Bb = sbB + s * (B_STAGE * 4);
        #pragma unroll
        for (int ks = 0; ks < 4; ++ks) {  // k-step of 8; chunk-offset bytes = ks*32
            const uint32_t koff = ks << 5;
            uint32_t a[2][4], b[2][4];
            #pragma unroll
            for (int mi = 0; mi < 2; mi++)
                ldmx4(a[mi], Ab + arow[mi] + (koff ^ axor[mi]));
            #pragma unroll
            for (int np = 0; np < 2; np++)
                ldmx4(b[np], Bb + brow[np] + (koff ^ bxor[np]));
            if (CVTA) {
                #pragma unroll
                for (int mi = 0; mi < 2; mi++)
                    #pragma unroll
                    for (int q = 0; q < 4; q++) a[mi][q] = tf32u(a[mi][q]);
            }
            #pragma unroll
            for (int mi = 0; mi < 2; mi++)
                #pragma unroll
                for (int ni = 0; ni < 4; ni++)
                    asm volatile(
                        "mma.sync.aligned.m16n8k8.row.col.f32.tf32.tf32.f32 "
                        "{%0,%1,%2,%3}, {%4,%5,%6,%7}, {%8,%9}, {%0,%1,%2,%3};\n"
                        : "+f"(acc[mi][ni][0]), "+f"(acc[mi][ni][1]),
                          "+f"(acc[mi][ni][2]), "+f"(acc[mi][ni][3])
                        : "r"(a[mi][0]), "r"(a[mi][1]), "r"(a[mi][2]), "r"(a[mi][3]),
                          "r"(b[ni >> 1][(ni & 1) * 2]), "r"(b[ni >> 1][(ni & 1) * 2 + 1]));
        }
    }

    // epilogue: float2 stores
    #pragma unroll
    for (int mi = 0; mi < 2; mi++) {
        const long r0 = m0 + wm * 32 + mi * 16 + g;
        #pragma unroll
        for (int ni = 0; ni < 4; ni++) {
            const int cc = n0 + wn * 32 + ni * 8 + 2 * tg;
            float b0 = 0.f, b1 = 0.f;
            if (MODE == 1) {
                b0 = __ldg(&g_bias[cc + 0]);
                b1 = __ldg(&g_bias[cc + 1]);
            }
            #pragma unroll
            for (int h = 0; h < 2; h++) {
                const long rr = r0 + h * 8;
                float x0 = acc[mi][ni][h * 2 + 0];
                float x1 = acc[mi][ni][h * 2 + 1];
                if (MODE == 1) {
                    x0 = to_tf32(x0 + b0);
                    x1 = to_tf32(x1 + b1);
                }
                if (MODE == 2) {
                    const long lim = rr - 4;
                    x0 = (cc + 0 <= lim) ? x0 * scale : -65000.f;
                    x1 = (cc + 1 <= lim) ? x1 * scale : -65000.f;
                }
                float2 v;
                v.x = x0;
                v.y = x1;
                *(float2*)(C + rr * ldc + cc) = v;
            }
        }
    }
}

// -------------------- masked softmax + decay combine -----------------------
// row i: allowed j in [0, i-4]; masked probs exactly 0 in fp32.
// rows i<4: uniform 1/T. Output rounded to tf32 (feeds K4).
__global__ __launch_bounds__(256) void softmax_combine(const float* __restrict__ decay) {
    const long row = blockIdx.x;
    const int i = (int)(row & (TT - 1));
    float* __restrict__ srow = g_scores + row * TT;
    const float* __restrict__ drow = decay + row * TT;
    const int t = threadIdx.x;
    const int L = (i >= 4) ? (i - 3) : 0;

    if (L == 0) {
        const float u = 0.3f / TT;
        for (int v = t; v < TT / 4; v += 256) {
            float4 d = ((const float4*)drow)[v];
            float4 o;
            o.x = to_tf32(fmaf(0.7f, d.x, u));
            o.y = to_tf32(fmaf(0.7f, d.y, u));
            o.z = to_tf32(fmaf(0.7f, d.z, u));
            o.w = to_tf32(fmaf(0.7f, d.w, u));
            ((float4*)srow)[v] = o;
        }
        return;
    }

    __shared__ float sh[TT];
    __shared__ float red[8];
    const int L4 = L >> 2;

    float mx = -3.4e38f;
    for (int v = t; v < L4; v += 256) {
        float4 f = ((const float4*)srow)[v];
        ((float4*)sh)[v] = f;
        mx = fmaxf(mx, fmaxf(fmaxf(f.x, f.y), fmaxf(f.z, f.w)));
    }
    for (int j = (L4 << 2) + t; j < L; j += 256) {
        float v = srow[j];
        sh[j] = v;
        mx = fmaxf(mx, v);
    }
    #pragma unroll
    for (int o = 16; o; o >>= 1) mx = fmaxf(mx, __shfl_xor_sync(0xffffffffu, mx, o));
    if ((t & 31) == 0) red[t >> 5] = mx;
    __syncthreads();
    mx = red[0];
    #pragma unroll
    for (int k = 1; k < 8; k++) mx = fmaxf(mx, red[k]);

    float sum = 0.f;
    for (int v = t; v < L4; v += 256) {
        float4 f = ((const float4*)sh)[v];
        f.x = __expf(f.x - mx);
        f.y = __expf(f.y - mx);
        f.z = __expf(f.z - mx);
        f.w = __expf(f.w - mx);
        ((float4*)sh)[v] = f;
        sum += f.x + f.y + f.z + f.w;
    }
    for (int j = (L4 << 2) + t; j < L; j += 256) {
        float e = __expf(sh[j] - mx);
        sh[j] = e;
        sum += e;
    }
    #pragma unroll
    for (int o = 16; o; o >>= 1) sum += __shfl_xor_sync(0xffffffffu, sum, o);
    __syncthreads();
    if ((t & 31) == 0) red[t >> 5] = sum;
    __syncthreads();
    sum = red[0];
    #pragma unroll
    for (int k = 1; k < 8; k++) sum += red[k];

    const float inv = 0.3f / sum;
    for (int v = t; v < L4; v += 256) {
        float4 p = ((const float4*)sh)[v];
        float4 d = ((const float4*)drow)[v];
        float4 o;
        o.x = to_tf32(fmaf(0.7f, d.x, p.x * inv));
        o.y = to_tf32(fmaf(0.7f, d.y, p.y * inv));
        o.z = to_tf32(fmaf(0.7f, d.z, p.z * inv));
        o.w = to_tf32(fmaf(0.7f, d.w, p.w * inv));
        ((float4*)srow)[v] = o;
    }
    const int Lup = (L + 3) & ~3;
    for (int j = (L4 << 2) + t; j < L; j += 256)
        srow[j] = to_tf32(fmaf(0.7f, drow[j], sh[j] * inv));
    for (int j = L + t; j < Lup && j < TT; j += 256)
        srow[j] = to_tf32(0.7f * drow[j]);
    for (int v = (Lup >> 2) + t; v < TT / 4; v += 256) {
        float4 d = ((const float4*)drow)[v];
        float4 o;
        o.x = to_tf32(0.7f * d.x);
        o.y = to_tf32(0.7f * d.y);
        o.z = to_tf32(0.7f * d.z);
        o.w = to_tf32(0.7f * d.w);
        ((float4*)srow)[v] = o;
    }
}

// --------------------------------- launch ----------------------------------
extern "C" void kernel_launch(void* const* d_in, const int* in_sizes, int n_in,
                              void* d_out, int out_size) {
    const float* hdc   = (const float*)d_in[0];
    const float* decay = (const float*)d_in[1];
    const float* Wq    = (const float*)d_in[2];
    const float* bq    = (const float*)d_in[3];
    const float* Wk    = (const float*)d_in[4];
    const float* bk    = (const float*)d_in[5];
    float* out = (float*)d_out;

    float *qk, *scores, *wptr, *hdcT;
    cudaGetSymbolAddress((void**)&qk, g_qk);
    cudaGetSymbolAddress((void**)&scores, g_scores);
    cudaGetSymbolAddress((void**)&wptr, g_w);
    cudaGetSymbolAddress((void**)&hdcT, g_hdcT);

    cudaFuncSetAttribute(gemm_mma<0, false>, cudaFuncAttributeMaxDynamicSharedMemorySize, SMEM_BYTES);
    cudaFuncSetAttribute(gemm_mma<1, true>, cudaFuncAttributeMaxDynamicSharedMemorySize, SMEM_BYTES);
    cudaFuncSetAttribute(gemm_mma<2, false>, cudaFuncAttributeMaxDynamicSharedMemorySize, SMEM_BYTES);

    pack_w<<<512, 256>>>(Wq, Wk, bq, bk);
    transpose_cvt<<<dim3(TT / 32, DD / 32, BB), dim3(32, 8)>>>(hdc);

    // K1: qk[16384,512] = hdc @ [Wq;Wk]^T + bias  (A rounded in-register)
    gemm_mma<1, true><<<dim3(512 / Bb_N, (BB * TT) / Bb_M, 1), NTH, SMEM_BYTES>>>(
        hdc, wptr, qk, DD, DD, DD, 2 * BOT, 0, 0, 0, 1.f);

    // K2: scores = mask(q @ k^T) / 16  (dead tiles skipped)
    gemm_mma<2, false><<<dim3(TT / Bb_N, TT / Bb_M, BB), NTH, SMEM_BYTES>>>(
        qk, qk + BOT, scores, BOT, 2 * BOT, 2 * BOT, TT,
        (long)TT * 2 * BOT, (long)TT * 2 * BOT, (long)TT * TT, 0.0625f);

    // K3: combined = 0.7*decay + 0.3*softmax  (in place)
    softmax_combine<<<BB * TT, 256>>>(decay);

    // K4: out = combined @ hdc  (B = hdcT, K-major)
    gemm_mma<0, false><<<dim3(DD / Bb_N, TT / Bb_M, BB), NTH, SMEM_BYTES>>>(
        scores, hdcT, out, TT, TT, TT, DD,
        (long)TT * TT, (long)DD * TT, (long)TT * DD, 1.f);
}